// round 17
// baseline (speedup 1.0000x reference)
#include <cuda_runtime.h>
#include <cuda_bf16.h>
#include <stdint.h>
#include <math.h>

#define SQ 2048
#define EM 512
#define NH 8
#define HD 64
#define EPSF 1e-15f

// ---------------- scratch (static device globals; no allocation) ----------------
__device__ float g_proj[3][SQ * EM];            // projected+normalized q/k/v points, [S][E]
__device__ __nv_bfloat16 g_bf[2][SQ * EM];      // bf16 copies of q,k points for attn MMA
__device__ __nv_bfloat16 g_vhi[SQ * EM];        // v split: hi part
__device__ __nv_bfloat16 g_vlo[SQ * EM];        // v split: lo part
__device__ __nv_bfloat16 g_xhi[3][SQ * EM];     // input x split planes
__device__ __nv_bfloat16 g_xlo[3][SQ * EM];
__device__ __nv_bfloat16 g_whi[3][EM * EM];     // weight W split planes
__device__ __nv_bfloat16 g_wlo[3][EM * EM];
__device__ float g_x2[3][SQ];
__device__ float g_zn[3][EM];
__device__ float g_chv[3][EM];
__device__ float g_shv[3][EM];
__device__ float g_pt2[3][NH * SQ];
__device__ float g_rinv[3][NH * SQ];

// ---------------- helpers ----------------
__device__ __forceinline__ uint32_t smem_u32(const void* p) {
    return (uint32_t)__cvta_generic_to_shared(p);
}
__device__ __forceinline__ float sqrt_ap(float x) {
    float r; asm("sqrt.approx.f32 %0, %1;" : "=f"(r) : "f"(x)); return r;
}
__device__ __forceinline__ float rcp_ap(float x) {
    float r; asm("rcp.approx.f32 %0, %1;" : "=f"(r) : "f"(x)); return r;
}
__device__ __forceinline__ void cp16(uint32_t dst, const void* src) {
    asm volatile("cp.async.cg.shared.global [%0], [%1], 16;" :: "r"(dst), "l"(src));
}
__device__ __forceinline__ void cp_commit() {
    asm volatile("cp.async.commit_group;");
}
__device__ __forceinline__ void cp_wait1() {
    asm volatile("cp.async.wait_group 1;");
}
__device__ __forceinline__ void ldsm4(uint32_t& a0, uint32_t& a1, uint32_t& a2, uint32_t& a3,
                                      uint32_t addr) {
    asm volatile("ldmatrix.sync.aligned.m8n8.x4.shared.b16 {%0,%1,%2,%3}, [%4];"
                 : "=r"(a0), "=r"(a1), "=r"(a2), "=r"(a3) : "r"(addr));
}
__device__ __forceinline__ void ldsm4t(uint32_t& a0, uint32_t& a1, uint32_t& a2, uint32_t& a3,
                                       uint32_t addr) {
    asm volatile("ldmatrix.sync.aligned.m8n8.x4.trans.shared.b16 {%0,%1,%2,%3}, [%4];"
                 : "=r"(a0), "=r"(a1), "=r"(a2), "=r"(a3) : "r"(addr));
}
__device__ __forceinline__ void mma16816(float* c, uint32_t a0, uint32_t a1, uint32_t a2,
                                         uint32_t a3, uint32_t b0, uint32_t b1) {
    asm volatile(
        "mma.sync.aligned.m16n8k16.row.col.f32.bf16.bf16.f32 "
        "{%0,%1,%2,%3}, {%4,%5,%6,%7}, {%8,%9}, {%0,%1,%2,%3};"
        : "+f"(c[0]), "+f"(c[1]), "+f"(c[2]), "+f"(c[3])
        : "r"(a0), "r"(a1), "r"(a2), "r"(a3), "r"(b0), "r"(b1));
}
__device__ __forceinline__ uint32_t packbf(__nv_bfloat16 a, __nv_bfloat16 b) {
    __nv_bfloat162 t; t.x = a; t.y = b;
    return *(uint32_t*)&t;
}

// ---------------- kernel 1: W column norms + bias cosh/sinh ----------------
__global__ void colnorm_k(const float* __restrict__ W0, const float* __restrict__ W1,
                          const float* __restrict__ W2, const float* __restrict__ b0,
                          const float* __restrict__ b1, const float* __restrict__ b2) {
    int t = blockIdx.y;
    int j = blockIdx.x * blockDim.x + threadIdx.x;
    if (j >= EM) return;
    const float* W = (t == 0) ? W0 : ((t == 1) ? W1 : W2);
    const float* b = (t == 0) ? b0 : ((t == 1) ? b1 : b2);
    float s = 0.f;
    for (int i = 0; i < EM; i++) { float v = W[i * EM + j]; s = fmaf(v, v, s); }
    float zn = fmaxf(sqrtf(s), EPSF);
    float r2 = 2.f * b[j];
    g_zn[t][j] = zn;
    g_chv[t][j] = coshf(r2);
    g_shv[t][j] = sinhf(r2);
}

// ---------------- kernel 2a: split inputs to bf16 hi/lo + row sumsq ----------------
__global__ void splitx_k(const float* __restrict__ x0, const float* __restrict__ x1,
                         const float* __restrict__ x2) {
    int t = blockIdx.y, s = blockIdx.x, tid = threadIdx.x;  // 128 threads
    const float* x = (t == 0) ? x0 : ((t == 1) ? x1 : x2);
    float4 v = ((const float4*)(x + (size_t)s * EM))[tid];
    float vv[4] = {v.x, v.y, v.z, v.w};
    float acc = v.x * v.x + v.y * v.y + v.z * v.z + v.w * v.w;
    #pragma unroll
    for (int m = 16; m; m >>= 1) acc += __shfl_xor_sync(0xffffffffu, acc, m);
    __shared__ float wsum[4];
    if ((tid & 31) == 0) wsum[tid >> 5] = acc;
    __nv_bfloat16* hdst = &g_xhi[t][(size_t)s * EM + tid * 4];
    __nv_bfloat16* ldst = &g_xlo[t][(size_t)s * EM + tid * 4];
    #pragma unroll
    for (int i = 0; i < 4; i++) {
        __nv_bfloat16 hi = __float2bfloat16(vv[i]);
        hdst[i] = hi;
        ldst[i] = __float2bfloat16(vv[i] - __bfloat162float(hi));
    }
    __syncthreads();
    if (tid == 0) g_x2[t][s] = wsum[0] + wsum[1] + wsum[2] + wsum[3];
}

// ---------------- kernel 2b: split weights to bf16 hi/lo ----------------
__global__ void splitw_k(const float* __restrict__ W0, const float* __restrict__ W1,
                         const float* __restrict__ W2) {
    int t = blockIdx.y, r = blockIdx.x, tid = threadIdx.x;  // 128 threads
    const float* W = (t == 0) ? W0 : ((t == 1) ? W1 : W2);
    float4 v = ((const float4*)(W + (size_t)r * EM))[tid];
    float vv[4] = {v.x, v.y, v.z, v.w};
    __nv_bfloat16* hdst = &g_whi[t][(size_t)r * EM + tid * 4];
    __nv_bfloat16* ldst = &g_wlo[t][(size_t)r * EM + tid * 4];
    #pragma unroll
    for (int i = 0; i < 4; i++) {
        __nv_bfloat16 hi = __float2bfloat16(vv[i]);
        hdst[i] = hi;
        ldst[i] = __float2bfloat16(vv[i] - __bfloat162float(hi));
    }
}

// ---------------- kernel 3: projection GEMM via bf16 MMA (128x64 block, pipelined) ----------------
#define BROW 144           // bf16 tile row stride in bytes (72 bf16)
// proj stage layout: Ahi[128x144] @0, Alo @18432, Whi[64x144] @36864, Wlo @46080
#define PST 55296
#define PROJ_SMEM_BYTES (2 * PST)

__global__ __launch_bounds__(256) void proj_mma_k() {
    int t = blockIdx.z;
    int n0 = blockIdx.x * 64, m0 = blockIdx.y * 128;
    extern __shared__ char psm[];
    uint32_t psb = smem_u32(psm);
    int tid = threadIdx.x;
    int l = tid & 31, w = tid >> 5;
    int wm0 = w << 4;          // m strip: w*16

    uint32_t aOff = (uint32_t)(wm0 + (l & 15)) * BROW + (uint32_t)((l >> 4) << 3) * 2;
    uint32_t bOff4 = (uint32_t)(l & 15) * BROW + (uint32_t)((l >> 4) << 4);

    // issue loads for chunk 0 into stage 0
    {
        #pragma unroll
        for (int p = 0; p < 4; p++) {           // A: 128 rows x 8 cp16
            int idx = tid + 256 * p;
            int row = idx >> 3, c16 = (idx & 7) * 8;
            size_t xsrc = (size_t)(m0 + row) * EM + c16;
            uint32_t d = psb + (uint32_t)(row * BROW + c16 * 2);
            cp16(d + 0,     &g_xhi[t][xsrc]);
            cp16(d + 18432, &g_xlo[t][xsrc]);
        }
        #pragma unroll
        for (int p = 0; p < 2; p++) {           // W: 64 rows x 8 cp16
            int idx = tid + 256 * p;
            int row = idx >> 3, c16 = (idx & 7) * 8;
            size_t wsrc = (size_t)row * EM + n0 + c16;
            uint32_t d = psb + 36864 + (uint32_t)(row * BROW + c16 * 2);
            cp16(d + 0,    &g_whi[t][wsrc]);
            cp16(d + 9216, &g_wlo[t][wsrc]);
        }
        cp_commit();
    }

    float C[8][4] = {};  // 8 n-frags of 16x8 (full n=64 per warp)

    for (int c = 0; c < 8; c++) {
        int s = c & 1;
        if (c < 7) {  // prefetch chunk c+1 into the other stage
            int k0n = (c + 1) * 64;
            uint32_t sb = psb + (uint32_t)((s ^ 1) * PST);
            #pragma unroll
            for (int p = 0; p < 4; p++) {
                int idx = tid + 256 * p;
                int row = idx >> 3, c16 = (idx & 7) * 8;
                size_t xsrc = (size_t)(m0 + row) * EM + k0n + c16;
                uint32_t d = sb + (uint32_t)(row * BROW + c16 * 2);
                cp16(d + 0,     &g_xhi[t][xsrc]);
                cp16(d + 18432, &g_xlo[t][xsrc]);
            }
            #pragma unroll
            for (int p = 0; p < 2; p++) {
                int idx = tid + 256 * p;
                int row = idx >> 3, c16 = (idx & 7) * 8;
                size_t wsrc = (size_t)(k0n + row) * EM + n0 + c16;
                uint32_t d = sb + 36864 + (uint32_t)(row * BROW + c16 * 2);
                cp16(d + 0,    &g_whi[t][wsrc]);
                cp16(d + 9216, &g_wlo[t][wsrc]);
            }
        }
        cp_commit();
        cp_wait1();
        __syncthreads();

        uint32_t aHb = psb + (uint32_t)(s * PST);
        uint32_t aLb = aHb + 18432;
        uint32_t wHb = aHb + 36864;
        uint32_t wLb = aHb + 46080;
        #pragma unroll
        for (int kc = 0; kc < 4; kc++) {
            uint32_t ah0, ah1, ah2, ah3, al0, al1, al2, al3;
            ldsm4(ah0, ah1, ah2, ah3, aHb + aOff + kc * 32);
            ldsm4(al0, al1, al2, al3, aLb + aOff + kc * 32);
            #pragma unroll
            for (int nt2 = 0; nt2 < 4; nt2++) {
                uint32_t bAddr = bOff4 + (uint32_t)(kc * 16) * BROW + nt2 * 32;
                uint32_t bh0, bh1, bh2, bh3, bl0, bl1, bl2, bl3;
                ldsm4t(bh0, bh1, bh2, bh3, wHb + bAddr);
                ldsm4t(bl0, bl1, bl2, bl3, wLb + bAddr);
                mma16816(C[nt2 * 2 + 0], ah0, ah1, ah2, ah3, bh0, bh1);
                mma16816(C[nt2 * 2 + 1], ah0, ah1, ah2, ah3, bh2, bh3);
                mma16816(C[nt2 * 2 + 0], ah0, ah1, ah2, ah3, bl0, bl1);
                mma16816(C[nt2 * 2 + 1], ah0, ah1, ah2, ah3, bl2, bl3);
                mma16816(C[nt2 * 2 + 0], al0, al1, al2, al3, bh0, bh1);
                mma16816(C[nt2 * 2 + 1], al0, al1, al2, al3, bh2, bh3);
            }
        }
        __syncthreads();
    }

    // h_linear epilogue in fragment layout
    int r0 = wm0 + (l >> 2), r1 = r0 + 8;
    float lam0 = 2.f / (1.f - g_x2[t][m0 + r0]);
    float lam1 = 2.f / (1.f - g_x2[t][m0 + r1]);
    #pragma unroll
    for (int nt = 0; nt < 8; nt++) {
        int c = n0 + nt * 8 + ((l & 3) << 1);
        float2 zn2 = *(float2*)&g_zn[t][c];
        float2 ch2 = *(float2*)&g_chv[t][c];
        float2 sh2 = *(float2*)&g_shv[t][c];
        float rzn0 = 1.f / zn2.x, rzn1 = 1.f / zn2.y;
        float vals[4] = {C[nt][0], C[nt][1], C[nt][2], C[nt][3]};
        float res[4];
        #pragma unroll
        for (int q = 0; q < 4; q++) {
            float lam = (q < 2) ? lam0 : lam1;
            float rzn = (q & 1) ? rzn1 : rzn0;
            float ch = (q & 1) ? ch2.y : ch2.x;
            float sh = (q & 1) ? sh2.y : sh2.x;
            float zn = (q & 1) ? zn2.y : zn2.x;
            float arg = (vals[q] * lam * rzn) * ch - (lam - 1.f) * sh;
            float as = __logf(arg + sqrt_ap(fmaf(arg, arg, 1.f)));   // asinh
            float dd = 2.f * zn * as;
            float e = __expf(dd);
            res[q] = 0.5f * (e - 1.f / e);                            // sinh
        }
        *(float2*)&g_proj[t][(size_t)(m0 + r0) * EM + c] = make_float2(res[0], res[1]);
        *(float2*)&g_proj[t][(size_t)(m0 + r1) * EM + c] = make_float2(res[2], res[3]);
    }
}

// ---------------- kernel 4: ball normalization + per-head aux + bf16 planes ----------------
__global__ void normaux_k() {
    int t = blockIdx.y, s = blockIdx.x, tid = threadIdx.x;  // 128 threads
    float* row = &g_proj[t][(size_t)s * EM];
    float4 v = ((float4*)row)[tid];
    float l4 = v.x * v.x + v.y * v.y + v.z * v.z + v.w * v.w;
    float tot = l4;
    #pragma unroll
    for (int m = 16; m; m >>= 1) tot += __shfl_xor_sync(0xffffffffu, tot, m);
    __shared__ float wsum[4];
    if ((tid & 31) == 0) wsum[tid >> 5] = tot;
    __syncthreads();
    float total = wsum[0] + wsum[1] + wsum[2] + wsum[3];
    float scale = 1.f / (1.f + sqrtf(1.f + total));
    v.x *= scale; v.y *= scale; v.z *= scale; v.w *= scale;
    ((float4*)row)[tid] = v;
    float vv[4] = {v.x, v.y, v.z, v.w};
    if (t < 2) {
        __nv_bfloat16* bdst = &g_bf[t][(size_t)s * EM + tid * 4];
        #pragma unroll
        for (int i = 0; i < 4; i++) bdst[i] = __float2bfloat16(vv[i]);
    } else {
        __nv_bfloat16* hdst = &g_vhi[(size_t)s * EM + tid * 4];
        __nv_bfloat16* ldst = &g_vlo[(size_t)s * EM + tid * 4];
        #pragma unroll
        for (int i = 0; i < 4; i++) {
            __nv_bfloat16 hi = __float2bfloat16(vv[i]);
            hdst[i] = hi;
            ldst[i] = __float2bfloat16(vv[i] - __bfloat162float(hi));
        }
    }
    float hs = l4;
    #pragma unroll
    for (int m = 8; m; m >>= 1) hs += __shfl_xor_sync(0xffffffffu, hs, m);
    if ((tid & 15) == 0) {
        int h = tid >> 4;
        float pt2 = scale * scale * hs;
        g_pt2[t][h * SQ + s] = pt2;
        g_rinv[t][h * SQ + s] = 1.f / (1.f - pt2);
    }
}

// ---------------- kernel 5: causal hyperbolic attention (full-MMA, pipelined) ----------------
// smem layout (bytes):
//  qB @0 (9216)
//  stage s (s=0,1): kB @9216+s*27648, vH @+9216, vL @+18432   (ends 64512)
//  q2s @64512, rqs @64768
//  aux stage s @65024+s*768: k2s +0, rks +256, rvs +512       (ends 66560)
//  denP [2][64] @66560                                         (ends 67072)
//  redS (f32 64x68) overlays @0 after the k-loop
#define ATTN_SMEM_BYTES 67072
#define AST 27648
#define RPAD 68

// w = exp(-tau*acosh(arg) - gamma); z = arg + sqrt((arg-1)(arg+1))
// fast path (tau==1): w = exp(-gamma) / z
__device__ __forceinline__ float wfun(float qk, float q2, float rq, float k2, float rk,
                                      int qg, int kg, float tau, float egam, bool fastp) {
    if (kg > qg) return 0.f;
    float d2 = fmaxf(q2 + k2 - 2.f * qk, 0.f);
    float arg = fmaf(2.f * d2, rq * rk, 1.f);
    arg = fmaxf(arg, 1.f + 1e-7f);
    float z = arg + sqrt_ap((arg - 1.f) * (arg + 1.f));
    if (fastp) return egam * rcp_ap(z);
    return egam * __expf(-tau * __logf(z));
}

__global__ __launch_bounds__(256) void attn_k(const float* __restrict__ stau,
                                              const float* __restrict__ sgam,
                                              float beta, float* __restrict__ out) {
    int bid = blockIdx.x;
    int h = bid & (NH - 1);
    int qt = (SQ / 64 - 1) - (bid >> 3);
    int q0 = qt * 64;
    extern __shared__ char sraw[];
    uint32_t sb = smem_u32(sraw);
    float* q2s = (float*)(sraw + 64512);
    float* rqs = (float*)(sraw + 64768);
    float* denP = (float*)(sraw + 66560);  // [2][64]

    int tid = threadIdx.x;
    int l = tid & 31, w = tid >> 5;
    int wq0 = (w >> 1) << 4;   // 0,16,32,48
    int wk0 = (w & 1) << 5;    // 0,32
    float tau = __expf(stau[0]);
    float egam = __expf(-sgam[0]);
    bool fastp = (tau == 1.0f);

    uint32_t aAddrBase = sb + (uint32_t)(wq0 + (l & 15)) * BROW + (uint32_t)((l >> 4) << 3) * 2;
    uint32_t b4Off = (uint32_t)((l & 7) + ((l & 16) >> 1)) * BROW + (uint32_t)(l & 8) * 2;
    uint32_t vOff4 = (uint32_t)(wk0 + (l & 15)) * BROW + (uint32_t)((l >> 4) << 4);

    int lrow = tid >> 3, lc8 = (tid & 7) * 8;  // loader mapping (p adds 32 rows)

    // issue k/v loads for kt=0 into stage 0 + aux
    {
        uint32_t st0 = sb + 9216;
        #pragma unroll
        for (int p = 0; p < 2; p++) {
            int r2 = lrow + 32 * p;
            size_t src = (size_t)r2 * EM + h * HD + lc8;
            uint32_t d = st0 + (uint32_t)(r2 * BROW + lc8 * 2);
            cp16(d + 0,     &g_bf[1][src]);
            cp16(d + 9216,  &g_vhi[src]);
            cp16(d + 18432, &g_vlo[src]);
        }
        if (tid < 48) {
            int grp = tid >> 4, sl = tid & 15;
            uint32_t d = sb + 65024 + (uint32_t)(grp * 256 + sl * 16);
            const float* src = (grp == 0) ? &g_pt2[1][h * SQ + sl * 4]
                             : (grp == 1) ? &g_rinv[1][h * SQ + sl * 4]
                                          : &g_rinv[2][h * SQ + sl * 4];
            cp16(d, src);
        }
        cp_commit();
    }

    // load q tile (bf16) + q aux (regular loads)
    {
        #pragma unroll
        for (int p = 0; p < 2; p++) {
            int r2 = lrow + 32 * p;
            *(uint4*)(sraw + r2 * BROW + lc8 * 2) =
                *(const uint4*)(&g_bf[0][(size_t)(q0 + r2) * EM + h * HD + lc8]);
        }
        if (tid < 64) {
            q2s[tid] = g_pt2[0][h * SQ + q0 + tid];
            rqs[tid] = g_rinv[0][h * SQ + q0 + tid];
        }
    }

    int r0 = wq0 + (l >> 2), r1 = r0 + 8;
    int qg0 = q0 + r0, qg1 = q0 + r1;

    float Cn[8][4] = {};          // num accumulator, 16q x 64hd per warp (its key half)
    float den2_0 = 0.f, den2_1 = 0.f;
    float q2a0 = 0.f, rqa0 = 0.f, q2a1 = 0.f, rqa1 = 0.f;

    for (int kt = 0; kt <= qt; kt++) {
        int s = kt & 1;
        if (kt < qt) {  // prefetch kt+1 into the other stage
            int k0n = (kt + 1) * 64;
            uint32_t stn = sb + 9216 + (uint32_t)((s ^ 1) * AST);
            #pragma unroll
            for (int p = 0; p < 2; p++) {
                int r2 = lrow + 32 * p;
                size_t src = (size_t)(k0n + r2) * EM + h * HD + lc8;
                uint32_t d = stn + (uint32_t)(r2 * BROW + lc8 * 2);
                cp16(d + 0,     &g_bf[1][src]);
                cp16(d + 9216,  &g_vhi[src]);
                cp16(d + 18432, &g_vlo[src]);
            }
            if (tid < 48) {
                int grp = tid >> 4, sl = tid & 15;
                uint32_t d = sb + 65024 + (uint32_t)((s ^ 1) * 768 + grp * 256 + sl * 16);
                const float* src = (grp == 0) ? &g_pt2[1][h * SQ + k0n + sl * 4]
                                 : (grp == 1) ? &g_rinv[1][h * SQ + k0n + sl * 4]
                                              : &g_rinv[2][h * SQ + k0n + sl * 4];
                cp16(d, src);
            }
        }
        cp_commit();
        cp_wait1();
        __syncthreads();

        if (kt == 0) {  // q aux now visible
            q2a0 = q2s[r0]; rqa0 = rqs[r0];
            q2a1 = q2s[r1]; rqa1 = rqs[r1];
        }
        int k0 = kt * 64;
        uint32_t kBb = sb + 9216 + (uint32_t)(s * AST);
        uint32_t vHb = kBb + 9216, vLb = kBb + 18432;
        float* k2s = (float*)(sraw + 65024 + s * 768);
        float* rks = k2s + 64;
        float* rvs = k2s + 128;

        // phase 1: S = Q.K^T via bf16 mma (warp tile 16q x 32k over hd=64)
        float sc[4][4];
        #pragma unroll
        for (int nb = 0; nb < 4; nb++)
            #pragma unroll
            for (int i = 0; i < 4; i++) sc[nb][i] = 0.f;
        #pragma unroll
        for (int kc = 0; kc < 4; kc++) {
            uint32_t a0, a1, a2, a3;
            ldsm4(a0, a1, a2, a3, aAddrBase + kc * 32);
            #pragma unroll
            for (int nb2 = 0; nb2 < 2; nb2++) {
                uint32_t b0, b1, b2, b3;
                ldsm4(b0, b1, b2, b3,
                      kBb + b4Off + (uint32_t)(wk0 + nb2 * 16) * BROW + kc * 32);
                mma16816(sc[nb2 * 2 + 0], a0, a1, a2, a3, b0, b1);
                mma16816(sc[nb2 * 2 + 1], a0, a1, a2, a3, b2, b3);
            }
        }

        // transform: distance -> exp weight -> wl split into bf16 A fragments
        uint32_t aHi[2][4], aLo[2][4];
        #pragma unroll
        for (int nb = 0; nb < 4; nb++) {
            int colb = wk0 + nb * 8 + ((l & 3) << 1);
            float2 k2p = *(float2*)&k2s[colb];
            float2 rkp = *(float2*)&rks[colb];
            float2 rvp = *(float2*)&rvs[colb];
            int kg = k0 + colb;
            float w00 = wfun(sc[nb][0], q2a0, rqa0, k2p.x, rkp.x, qg0, kg,     tau, egam, fastp);
            float w01 = wfun(sc[nb][1], q2a0, rqa0, k2p.y, rkp.y, qg0, kg + 1, tau, egam, fastp);
            float w10 = wfun(sc[nb][2], q2a1, rqa1, k2p.x, rkp.x, qg1, kg,     tau, egam, fastp);
            float w11 = wfun(sc[nb][3], q2a1, rqa1, k2p.y, rkp.y, qg1, kg + 1, tau, egam, fastp);
            float lv0 = 2.f * rvp.x, lv1 = 2.f * rvp.y;
            float wl00 = w00 * lv0, wl01 = w01 * lv1;
            float wl10 = w10 * lv0, wl11 = w11 * lv1;
            den2_0 += (wl00 - w00) + (wl01 - w01);
            den2_1 += (wl10 - w10) + (wl11 - w11);
            __nv_bfloat16 h00 = __float2bfloat16(wl00), h01 = __float2bfloat16(wl01);
            __nv_bfloat16 h10 = __float2bfloat16(wl10), h11 = __float2bfloat16(wl11);
            __nv_bfloat16 e00 = __float2bfloat16(wl00 - __bfloat162float(h00));
            __nv_bfloat16 e01 = __float2bfloat16(wl01 - __bfloat162float(h01));
            __nv_bfloat16 e10 = __float2bfloat16(wl10 - __bfloat162float(h10));
            __nv_bfloat16 e11 = __float2bfloat16(wl11 - __bfloat162float(h11));
            int kc = nb >> 1, ri = (nb & 1) << 1;
            aHi[kc][ri + 0] = packbf(h00, h01);
            aHi[kc][ri + 1] = packbf(h10, h11);
            aLo[kc][ri + 0] = packbf(e00, e01);
            aLo[kc][ri + 1] = packbf(e10, e11);
        }

        // phase 2: num += W_l . V via mma (A = wl fragments, B = v hi/lo, 3-way split)
        #pragma unroll
        for (int kc = 0; kc < 2; kc++) {
            uint32_t baseH = vHb + vOff4 + (uint32_t)(kc * 16) * BROW;
            uint32_t baseL = vLb + vOff4 + (uint32_t)(kc * 16) * BROW;
            #pragma unroll
            for (int nt2 = 0; nt2 < 4; nt2++) {
                uint32_t bh0, bh1, bh2, bh3, bl0, bl1, bl2, bl3;
                ldsm4t(bh0, bh1, bh2, bh3, baseH + nt2 * 32);
                ldsm4t(bl0, bl1, bl2, bl3, baseL + nt2 * 32);
                mma16816(Cn[nt2 * 2 + 0], aHi[kc][0], aHi[kc][1], aHi[kc][2], aHi[kc][3], bh0, bh1);
                mma16816(Cn[nt2 * 2 + 1], aHi[kc][0], aHi[kc][1], aHi[kc][2], aHi[kc][3], bh2, bh3);
                mma16816(Cn[nt2 * 2 + 0], aHi[kc][0], aHi[kc][1], aHi[kc][2], aHi[kc][3], bl0, bl1);
                mma16816(Cn[nt2 * 2 + 1], aHi[kc][0], aHi[kc][1], aHi[kc][2], aHi[kc][3], bl2, bl3);
                mma16816(Cn[nt2 * 2 + 0], aLo[kc][0], aLo[kc][1], aLo[kc][2], aLo[kc][3], bh0, bh1);
                mma16816(Cn[nt2 * 2 + 1], aLo[kc][0], aLo[kc][1], aLo[kc][2], aLo[kc][3], bh2, bh3);
            }
        }
        __syncthreads();
    }

    // fold den partials (quad lanes share rows), stage per key-half
    den2_0 += __shfl_xor_sync(0xffffffffu, den2_0, 1);
    den2_0 += __shfl_xor_sync(0xffffffffu, den2_0, 2);
    den2_1 += __shfl_xor_sync(0xffffffffu, den2_1, 1);
    den2_1 += __shfl_xor_sync(0xffffffffu, den2_1, 2);
    if ((l & 3) == 0) {
        denP[(w & 1) * 64 + r0] = den2_0;
        denP[(w & 1) * 64 + r1] = den2_1;
    }
    __syncthreads();

    // cross-warp num reduction: odd (wk0=32) warps stage, even warps add
    float* redS = (float*)sraw;  // 64 x RPAD, overlays qB/stage0
    if (w & 1) {
        #pragma unroll
        for (int nt = 0; nt < 8; nt++) {
            int c = nt * 8 + ((l & 3) << 1);
            *(float2*)&redS[r0 * RPAD + c] = make_float2(Cn[nt][0], Cn[nt][1]);
            *(float2*)&redS[r1 * RPAD + c] = make_float2(Cn[nt][2], Cn[nt][3]);
        }
    }
    __syncthreads();
    if (!(w & 1)) {
        #pragma unroll
        for (int nt = 0; nt < 8; nt++) {
            int c = nt * 8 + ((l & 3) << 1);
            float2 p0 = *(float2*)&redS[r0 * RPAD + c];
            float2 p1 = *(float2*)&redS[r1 * RPAD + c];
            Cn[nt][0] += p0.x; Cn[nt][1] += p0.y;
            Cn[nt][2] += p1.x; Cn[nt][3] += p1.y;
        }
        // epilogue in fragment layout: rows r0, r1
        #pragma unroll
        for (int half = 0; half < 2; half++) {
            int r = half ? r1 : r0;
            float d = fmaxf(denP[r] + denP[64 + r], EPSF);
            float inv = 1.f / d;
            float gv[16];
            float gs = 0.f;
            #pragma unroll
            for (int nt = 0; nt < 8; nt++) {
                float g0 = Cn[nt][half * 2 + 0] * inv;
                float g1 = Cn[nt][half * 2 + 1] * inv;
                gv[nt * 2] = g0; gv[nt * 2 + 1] = g1;
                gs += g0 * g0 + g1 * g1;
            }
            gs += __shfl_xor_sync(0xffffffffu, gs, 1);
            gs += __shfl_xor_sync(0xffffffffu, gs, 2);
            float gn = fmaxf(sqrtf(gs), EPSF);
            float xc = fminf(gn, 1.f - 1e-7f);
            float tt = xc / (1.f + sqrtf(1.f - xc * xc));  // tanh(0.5*atanh(xc))
            float f = beta * tt / gn;
            float* orow = out + (size_t)(q0 + r) * EM + h * HD;
            #pragma unroll
            for (int nt = 0; nt < 8; nt++) {
                int c = nt * 8 + ((l & 3) << 1);
                *(float2*)&orow[c] = make_float2(f * gv[nt * 2], f * gv[nt * 2 + 1]);
            }
        }
    }
}

// ---------------- launch ----------------
extern "C" void kernel_launch(void* const* d_in, const int* in_sizes, int n_in,
                              void* d_out, int out_size) {
    const float* q  = (const float*)d_in[0];
    const float* k  = (const float*)d_in[1];
    const float* v  = (const float*)d_in[2];
    const float* Wq = (const float*)d_in[3];
    const float* Wk = (const float*)d_in[4];
    const float* Wv = (const float*)d_in[5];
    const float* bq = (const float*)d_in[6];
    const float* bk = (const float*)d_in[7];
    const float* bv = (const float*)d_in[8];
    const float* st = (const float*)d_in[9];
    const float* sg = (const float*)d_in[10];
    float* out = (float*)d_out;

    double lb = (lgamma(256.0) + lgamma(0.5) - lgamma(256.5))
              - (lgamma(32.0) + lgamma(0.5) - lgamma(32.5));
    float beta = (float)exp(lb);

    cudaFuncSetAttribute(attn_k, cudaFuncAttributeMaxDynamicSharedMemorySize, ATTN_SMEM_BYTES);
    cudaFuncSetAttribute(proj_mma_k, cudaFuncAttributeMaxDynamicSharedMemorySize,
                         PROJ_SMEM_BYTES);

    colnorm_k<<<dim3(2, 3), 256>>>(Wq, Wk, Wv, bq, bk, bv);
    splitx_k<<<dim3(SQ, 3), 128>>>(q, k, v);
    splitw_k<<<dim3(EM, 3), 128>>>(Wq, Wk, Wv);
    proj_mma_k<<<dim3(EM / 64, SQ / 128, 3), 256, PROJ_SMEM_BYTES>>>();
    normaux_k<<<dim3(SQ, 3), 128>>>();
    attn_k<<<(SQ / 64) * NH, 256, ATTN_SMEM_BYTES>>>(st, sg, beta, out);
    (void)in_sizes; (void)n_in; (void)out_size;
}